// round 16
// baseline (speedup 1.0000x reference)
#include <cuda_runtime.h>
#include <cuda_bf16.h>
#include <cstdint>

#define NNODES 50000
#define MAXE   800000
#define IN_C   512
#define HID_C  256
#define OUT_C  128

// ---------------------------------------------------------------------------
// Scratch (device globals — allocation is forbidden)
// ---------------------------------------------------------------------------
__device__ float g_H1[(size_t)NNODES * HID_C];
__device__ float g_A1[(size_t)NNODES * HID_C];
__device__ float g_H2[(size_t)NNODES * OUT_C];
__device__ int   g_CNT[NNODES];
__device__ float g_DINV[NNODES];
__device__ int   g_ROWPTR[NNODES + 1];
__device__ int   g_CUR[NNODES];
__device__ int   g_BSUM[256];
__device__ int2  g_ADJ[MAXE];
__device__ int   g_is64;
// Pre-split, pre-transposed weights: Wt[n][k] (K-major = mma .col layout)
__device__ __nv_bfloat16 g_W1h[HID_C * IN_C];
__device__ __nv_bfloat16 g_W1l[HID_C * IN_C];
__device__ __nv_bfloat16 g_W2h[OUT_C * HID_C];
__device__ __nv_bfloat16 g_W2l[OUT_C * HID_C];

// ---------------------------------------------------------------------------
// PTX helpers
// ---------------------------------------------------------------------------
__device__ __forceinline__ uint32_t smem_u32(const void* p) {
    uint32_t a;
    asm("{ .reg .u64 t; cvta.to.shared.u64 t, %1; cvt.u32.u64 %0, t; }" : "=r"(a) : "l"(p));
    return a;
}

#define LDMX4(r, addr) \
    asm volatile("ldmatrix.sync.aligned.m8n8.x4.shared.b16 {%0,%1,%2,%3}, [%4];" \
        : "=r"((r)[0]), "=r"((r)[1]), "=r"((r)[2]), "=r"((r)[3]) : "r"(addr))

#define MMA16816(d, a, b0, b1) \
    asm volatile("mma.sync.aligned.m16n8k16.row.col.f32.bf16.bf16.f32 " \
        "{%0,%1,%2,%3}, {%4,%5,%6,%7}, {%8,%9}, {%0,%1,%2,%3};" \
        : "+f"((d)[0]), "+f"((d)[1]), "+f"((d)[2]), "+f"((d)[3]) \
        : "r"((a)[0]), "r"((a)[1]), "r"((a)[2]), "r"((a)[3]), "r"(b0), "r"(b1))

// ---------------------------------------------------------------------------
// Edge index decoding (int64 vs int32, detected once per launch)
// ---------------------------------------------------------------------------
__device__ __forceinline__ int edge_at(const void* ei, long long i, int is64) {
    if (is64) return (int)((const long long*)ei)[i];
    return ((const int*)ei)[i];
}

__global__ void detect_kernel(const void* ei, long long maxv) {
    const long long* p = (const long long*)ei;
    int ok64 = 1;
    #pragma unroll
    for (int i = 0; i < 8; i++) {
        long long v = p[i];
        if (v < 0 || v >= maxv) ok64 = 0;
    }
    g_is64 = ok64;
}

// ---------------------------------------------------------------------------
// CSR build
// ---------------------------------------------------------------------------
__global__ void zero_cnt_kernel(int* p, int n) {
    int i = blockIdx.x * blockDim.x + threadIdx.x;
    if (i < n) p[i] = 0;
}

__global__ void hist_kernel(const void* __restrict__ ei, int* __restrict__ cnt, int E) {
    int e = (blockIdx.x * blockDim.x + threadIdx.x) * 2;
    if (e + 1 < E) {
        int d0 = edge_at(ei, (long long)E + e,     g_is64);
        int d1 = edge_at(ei, (long long)E + e + 1, g_is64);
        atomicAdd(&cnt[d0], 1);
        atomicAdd(&cnt[d1], 1);
    } else if (e < E) {
        atomicAdd(&cnt[edge_at(ei, (long long)E + e, g_is64)], 1);
    }
}

__global__ void dinv_kernel(const int* __restrict__ cnt, float* __restrict__ dinv, int n) {
    int i = blockIdx.x * blockDim.x + threadIdx.x;
    if (i < n) dinv[i] = rsqrtf((float)cnt[i] + 1.0f);
}

__global__ void scan1_kernel(const int* __restrict__ cnt, int* __restrict__ locex,
                             int* __restrict__ bsum, int n)
{
    __shared__ int sh[256];
    int t = threadIdx.x;
    int i = blockIdx.x * 256 + t;
    int v = (i < n) ? cnt[i] : 0;
    sh[t] = v;
    __syncthreads();
    #pragma unroll
    for (int off = 1; off < 256; off <<= 1) {
        int u = (t >= off) ? sh[t - off] : 0;
        __syncthreads();
        sh[t] += u;
        __syncthreads();
    }
    if (i < n) locex[i] = sh[t] - v;
    if (t == 255) bsum[blockIdx.x] = sh[255];
}

__global__ void scan2_kernel(int* __restrict__ bsum, int nb)
{
    __shared__ int sh[256];
    int t = threadIdx.x;
    int v = (t < nb) ? bsum[t] : 0;
    sh[t] = v;
    __syncthreads();
    #pragma unroll
    for (int off = 1; off < 256; off <<= 1) {
        int u = (t >= off) ? sh[t - off] : 0;
        __syncthreads();
        sh[t] += u;
        __syncthreads();
    }
    if (t < nb) bsum[t] = sh[t] - v;
}

__global__ void scan3_kernel(int* __restrict__ rowptr, const int* __restrict__ bsum,
                             int* __restrict__ cur, int n, int E)
{
    int i = blockIdx.x * 256 + (int)threadIdx.x;
    if (i < n) {
        int r = rowptr[i] + bsum[blockIdx.x];
        rowptr[i] = r;
        cur[i] = r;
    }
    if (i == 0) rowptr[n] = E;
}

__global__ void fill_kernel(const void* __restrict__ ei, const float* __restrict__ dinv,
                            int* __restrict__ cur, int2* __restrict__ adj, int E)
{
    int e = blockIdx.x * blockDim.x + threadIdx.x;
    if (e >= E) return;
    int is64 = g_is64;
    int s = edge_at(ei, e, is64);
    int d = edge_at(ei, (long long)E + e, is64);
    int pos = atomicAdd(&cur[d], 1);
    float w = dinv[s] * dinv[d];
    adj[pos] = make_int2(s, __float_as_int(w));
}

// ---------------------------------------------------------------------------
// Weight prep: W[k][n] (fp32) -> Wt_hi/Wt_lo[n][k] (bf16, K-major)
// ---------------------------------------------------------------------------
__global__ void prep_w_kernel(const float* __restrict__ W,
                              __nv_bfloat16* __restrict__ Wh,
                              __nv_bfloat16* __restrict__ Wl, int K, int N)
{
    int idx = blockIdx.x * blockDim.x + threadIdx.x;
    if (idx >= K * N) return;
    int n = idx / K, k = idx - n * K;
    float w = W[(size_t)k * N + n];
    __nv_bfloat16 h = __float2bfloat16_rn(w);
    float lo = w - __bfloat162float(h);
    Wh[idx] = h;
    Wl[idx] = __float2bfloat16_rn(lo);
}

// ---------------------------------------------------------------------------
// mma.sync bf16 3-product GEMM, double-buffered smem + register prefetch.
// C[M,N] (+)= A[M, kLen]@Wt[N, kLen]^T, row strides kStride.
// CTA tile 128x128, BK=32, 256 threads, 8 warps 2m x 4n (warp 64x32).
// ACCUM: epilogue reads C and adds (for K-split partial accumulation).
// ---------------------------------------------------------------------------
#define SSTR 40

template<int BN, bool ACCUM>
__global__ __launch_bounds__(256) void gemm_mma_kernel(
    const float* __restrict__ A,
    const __nv_bfloat16* __restrict__ Wh, const __nv_bfloat16* __restrict__ Wl,
    float* __restrict__ C, int M, int kStride, int kLen, int Nn, int nOff)
{
    constexpr int TAe = 128 * SSTR;
    constexpr int TBe = BN * SSTR;
    constexpr int MT  = (BN == 128) ? 4 : 2;
    constexpr int RB  = BN / 64;

    extern __shared__ __nv_bfloat16 dsm[];
    __nv_bfloat16* sAh[2] = { dsm,            dsm + TAe };
    __nv_bfloat16* sAl[2] = { dsm + 2 * TAe,  dsm + 3 * TAe };
    __nv_bfloat16* sBh[2] = { dsm + 4 * TAe,  dsm + 4 * TAe + TBe };
    __nv_bfloat16* sBl[2] = { dsm + 4 * TAe + 2 * TBe, dsm + 4 * TAe + 3 * TBe };

    const int tid  = threadIdx.x;
    const int wid  = tid >> 5;
    const int lane = tid & 31;
    const int rowBase = blockIdx.y * 128;
    const int colBase = blockIdx.x * BN + nOff;
    const int warpM = (BN == 128) ? (wid & 1) * 64 : (wid & 3) * 32;
    const int warpN = (BN == 128) ? (wid >> 1) * 32 : (wid >> 2) * 32;

    const uint32_t base = smem_u32(dsm);
    const uint32_t uAh[2] = { base,                     base + TAe * 2 };
    const uint32_t uAl[2] = { base + 4 * TAe,           base + 6 * TAe };
    const uint32_t uBh[2] = { base + 8 * TAe,           base + 8 * TAe + TBe * 2 };
    const uint32_t uBl[2] = { base + 8 * TAe + 4 * TBe, base + 8 * TAe + 6 * TBe };

    const int lrA = lane & 15;
    const int lkA = (lane >> 4) << 3;
    const int lnB = (lane & 7) + ((lane >> 4) << 3);
    const int lkB = ((lane >> 3) & 1) << 3;

    const int aRow = tid >> 1, aCol = (tid & 1) * 16;
    const int bRow = tid >> 2, bCol = (tid & 3) * 8;
    const bool aOk = (rowBase + aRow) < M;

    float acc[MT][4][4];
    #pragma unroll
    for (int mt = 0; mt < MT; mt++)
        #pragma unroll
        for (int nt = 0; nt < 4; nt++)
            #pragma unroll
            for (int i = 0; i < 4; i++) acc[mt][nt][i] = 0.0f;

    float4 aR[4];
    uint4  bhR[RB], blR[RB];

    auto loadT = [&](int k0) {
        const float* arow = A + (size_t)(rowBase + aRow) * kStride + k0 + aCol;
        #pragma unroll
        for (int i = 0; i < 4; i++)
            aR[i] = aOk ? *(const float4*)(arow + i * 4) : make_float4(0.f, 0.f, 0.f, 0.f);
        #pragma unroll
        for (int r2 = 0; r2 < RB; r2++) {
            const size_t gb = (size_t)(colBase + bRow + r2 * 64) * kStride + k0 + bCol;
            bhR[r2] = *(const uint4*)(Wh + gb);
            blR[r2] = *(const uint4*)(Wl + gb);
        }
    };

    auto storeT = [&](int buf) {
        #pragma unroll
        for (int i = 0; i < 4; i++) {
            float4 v = aR[i];
            __nv_bfloat162 h0 = __floats2bfloat162_rn(v.x, v.y);
            __nv_bfloat162 h1 = __floats2bfloat162_rn(v.z, v.w);
            __nv_bfloat162 l0 = __floats2bfloat162_rn(v.x - __bfloat162float(h0.x),
                                                      v.y - __bfloat162float(h0.y));
            __nv_bfloat162 l1 = __floats2bfloat162_rn(v.z - __bfloat162float(h1.x),
                                                      v.w - __bfloat162float(h1.y));
            int off = aRow * SSTR + aCol + i * 4;
            *(__nv_bfloat162*)&sAh[buf][off]     = h0;
            *(__nv_bfloat162*)&sAh[buf][off + 2] = h1;
            *(__nv_bfloat162*)&sAl[buf][off]     = l0;
            *(__nv_bfloat162*)&sAl[buf][off + 2] = l1;
        }
        #pragma unroll
        for (int r2 = 0; r2 < RB; r2++) {
            int off = (bRow + r2 * 64) * SSTR + bCol;
            *(uint4*)&sBh[buf][off] = bhR[r2];
            *(uint4*)&sBl[buf][off] = blR[r2];
        }
    };

    auto compute = [&](int buf) {
        #pragma unroll
        for (int ks = 0; ks < 2; ks++) {
            uint32_t ah[MT][4], al[MT][4], bh[2][4], bl[2][4];
            #pragma unroll
            for (int mt = 0; mt < MT; mt++) {
                uint32_t off = (uint32_t)((warpM + mt * 16 + lrA) * SSTR + ks * 16 + lkA) * 2;
                LDMX4(ah[mt], uAh[buf] + off);
                LDMX4(al[mt], uAl[buf] + off);
            }
            #pragma unroll
            for (int np = 0; np < 2; np++) {
                uint32_t off = (uint32_t)((warpN + np * 16 + lnB) * SSTR + ks * 16 + lkB) * 2;
                LDMX4(bh[np], uBh[buf] + off);
                LDMX4(bl[np], uBl[buf] + off);
            }
            #pragma unroll
            for (int mt = 0; mt < MT; mt++)
                #pragma unroll
                for (int np = 0; np < 2; np++)
                    #pragma unroll
                    for (int h = 0; h < 2; h++) {
                        int nt = np * 2 + h;
                        MMA16816(acc[mt][nt], ah[mt], bh[np][h*2], bh[np][h*2+1]);
                        MMA16816(acc[mt][nt], ah[mt], bl[np][h*2], bl[np][h*2+1]);
                        MMA16816(acc[mt][nt], al[mt], bh[np][h*2], bh[np][h*2+1]);
                    }
        }
    };

    const int KI = kLen >> 5;

    loadT(0);
    storeT(0);
    __syncthreads();
    if (KI > 1) loadT(32);

    for (int it = 0; it < KI; it++) {
        compute(it & 1);
        if (it + 1 < KI) {
            storeT((it + 1) & 1);
            __syncthreads();
            if (it + 2 < KI) loadT((it + 2) << 5);
        }
    }

    #pragma unroll
    for (int mt = 0; mt < MT; mt++) {
        int r0 = rowBase + warpM + mt * 16 + (lane >> 2);
        int r1 = r0 + 8;
        #pragma unroll
        for (int nt = 0; nt < 4; nt++) {
            int c = colBase + warpN + nt * 8 + (lane & 3) * 2;
            if (r0 < M) {
                float2 v = make_float2(acc[mt][nt][0], acc[mt][nt][1]);
                float2* p = (float2*)&C[(size_t)r0 * Nn + c];
                if (ACCUM) { float2 o = *p; v.x += o.x; v.y += o.y; }
                *p = v;
            }
            if (r1 < M) {
                float2 v = make_float2(acc[mt][nt][2], acc[mt][nt][3]);
                float2* p = (float2*)&C[(size_t)r1 * Nn + c];
                if (ACCUM) { float2 o = *p; v.x += o.x; v.y += o.y; }
                *p = v;
            }
        }
    }
}

#define SMEM_BN128 ((4 * 128 * SSTR + 4 * 128 * SSTR) * 2)   // 81920

// ---------------------------------------------------------------------------
// CSR gather over a feature window [f4base, f4base+blockDim.x) (float4 units).
// ---------------------------------------------------------------------------
template<int C, int NPB, bool RELU>
__global__ __launch_bounds__(256) void gather4_kernel(
    const float4* __restrict__ H4, const int* __restrict__ rowptr,
    const int2* __restrict__ adj, const float* __restrict__ dinv,
    const float4* __restrict__ bias4, float4* __restrict__ out4, int f4base)
{
    const int F4 = C / 4;
    int v  = blockIdx.x * NPB + threadIdx.y;
    int fx = f4base + threadIdx.x;
    if (v >= NNODES) return;

    float dv = dinv[v];
    float ws = dv * dv;
    float4 acc = H4[(size_t)v * F4 + fx];
    acc.x *= ws; acc.y *= ws; acc.z *= ws; acc.w *= ws;

    int j   = rowptr[v];
    int end = rowptr[v + 1];

    for (; j + 3 < end; j += 4) {
        int2 a0 = __ldg(&adj[j]);
        int2 a1 = __ldg(&adj[j + 1]);
        int2 a2 = __ldg(&adj[j + 2]);
        int2 a3 = __ldg(&adj[j + 3]);
        float4 h0 = H4[(size_t)a0.x * F4 + fx];
        float4 h1 = H4[(size_t)a1.x * F4 + fx];
        float4 h2 = H4[(size_t)a2.x * F4 + fx];
        float4 h3 = H4[(size_t)a3.x * F4 + fx];
        float w0 = __int_as_float(a0.y), w1 = __int_as_float(a1.y);
        float w2 = __int_as_float(a2.y), w3 = __int_as_float(a3.y);
        acc.x = fmaf(h0.x, w0, fmaf(h1.x, w1, fmaf(h2.x, w2, fmaf(h3.x, w3, acc.x))));
        acc.y = fmaf(h0.y, w0, fmaf(h1.y, w1, fmaf(h2.y, w2, fmaf(h3.y, w3, acc.y))));
        acc.z = fmaf(h0.z, w0, fmaf(h1.z, w1, fmaf(h2.z, w2, fmaf(h3.z, w3, acc.z))));
        acc.w = fmaf(h0.w, w0, fmaf(h1.w, w1, fmaf(h2.w, w2, fmaf(h3.w, w3, acc.w))));
    }
    for (; j < end; j++) {
        int2 a0 = __ldg(&adj[j]);
        float4 h0 = H4[(size_t)a0.x * F4 + fx];
        float w0 = __int_as_float(a0.y);
        acc.x = fmaf(h0.x, w0, acc.x);
        acc.y = fmaf(h0.y, w0, acc.y);
        acc.z = fmaf(h0.z, w0, acc.z);
        acc.w = fmaf(h0.w, w0, acc.w);
    }

    float4 b = bias4[fx];
    acc.x += b.x; acc.y += b.y; acc.z += b.z; acc.w += b.w;
    if (RELU) {
        acc.x = fmaxf(acc.x, 0.f); acc.y = fmaxf(acc.y, 0.f);
        acc.z = fmaxf(acc.z, 0.f); acc.w = fmaxf(acc.w, 0.f);
    }
    out4[(size_t)v * F4 + fx] = acc;
}

// ---------------------------------------------------------------------------
// Launch schedule (K-split gemm2):
//   s1 : prep_w2, CSR chain, [e1a] gather1a(f0-127), gemm2K0, rec eK0,
//        [e2k1] gather2a, rec eS2
//   main: prep_w1, gemm1a, rec e1a, gemm1b, [eJoin] gather1b(f128-255),
//        [eK0] gemm2K1(accum), rec e2k1, gather2b, [eS2]
// ---------------------------------------------------------------------------
extern "C" void kernel_launch(void* const* d_in, const int* in_sizes, int n_in,
                              void* d_out, int out_size)
{
    const float* x  = (const float*)d_in[0];
    const void*  ei = d_in[1];
    const float* W1 = (const float*)d_in[2];
    const float* b1 = (const float*)d_in[3];
    const float* W2 = (const float*)d_in[4];
    const float* b2 = (const float*)d_in[5];
    float* out = (float*)d_out;

    const int E = in_sizes[1] / 2;

    float *H1, *A1, *H2, *DINV;
    int *CNT, *ROWPTR, *CUR, *BSUM;
    int2 *ADJ;
    __nv_bfloat16 *W1h, *W1l, *W2h, *W2l;
    cudaGetSymbolAddress((void**)&H1,     g_H1);
    cudaGetSymbolAddress((void**)&A1,     g_A1);
    cudaGetSymbolAddress((void**)&H2,     g_H2);
    cudaGetSymbolAddress((void**)&CNT,    g_CNT);
    cudaGetSymbolAddress((void**)&DINV,   g_DINV);
    cudaGetSymbolAddress((void**)&ROWPTR, g_ROWPTR);
    cudaGetSymbolAddress((void**)&CUR,    g_CUR);
    cudaGetSymbolAddress((void**)&BSUM,   g_BSUM);
    cudaGetSymbolAddress((void**)&ADJ,    g_ADJ);
    cudaGetSymbolAddress((void**)&W1h,    g_W1h);
    cudaGetSymbolAddress((void**)&W1l,    g_W1l);
    cudaGetSymbolAddress((void**)&W2h,    g_W2h);
    cudaGetSymbolAddress((void**)&W2l,    g_W2l);

    cudaFuncSetAttribute((const void*)gemm_mma_kernel<128, false>,
                         cudaFuncAttributeMaxDynamicSharedMemorySize, SMEM_BN128);
    cudaFuncSetAttribute((const void*)gemm_mma_kernel<128, true>,
                         cudaFuncAttributeMaxDynamicSharedMemorySize, SMEM_BN128);

    static cudaStream_t s1 = nullptr;
    static cudaEvent_t  eFork = nullptr, eJoin = nullptr, e1a = nullptr,
                        eK0 = nullptr, e2k1 = nullptr, eS2 = nullptr;
    if (s1 == nullptr) {
        cudaStreamCreateWithFlags(&s1, cudaStreamNonBlocking);
        cudaEventCreateWithFlags(&eFork, cudaEventDisableTiming);
        cudaEventCreateWithFlags(&eJoin, cudaEventDisableTiming);
        cudaEventCreateWithFlags(&e1a,   cudaEventDisableTiming);
        cudaEventCreateWithFlags(&eK0,   cudaEventDisableTiming);
        cudaEventCreateWithFlags(&e2k1,  cudaEventDisableTiming);
        cudaEventCreateWithFlags(&eS2,   cudaEventDisableTiming);
    }

    const int T = 256;
    const int NB = (NNODES + 255) / 256;   // 196
    const int MB = (NNODES + 127) / 128;   // 391

    // --- fork: W2 prep + CSR build on s1 ---
    cudaEventRecord(eFork, 0);
    cudaStreamWaitEvent(s1, eFork, 0);

    prep_w_kernel<<<(HID_C * OUT_C + T - 1) / T, T, 0, s1>>>(W2, W2h, W2l, HID_C, OUT_C);
    detect_kernel<<<1, 1, 0, s1>>>(ei, (long long)NNODES);
    zero_cnt_kernel<<<NB, T, 0, s1>>>(CNT, NNODES);
    hist_kernel<<<(E / 2 + T) / T, T, 0, s1>>>(ei, CNT, E);
    dinv_kernel<<<NB, T, 0, s1>>>(CNT, DINV, NNODES);
    scan1_kernel<<<NB, 256, 0, s1>>>(CNT, ROWPTR, BSUM, NNODES);
    scan2_kernel<<<1, 256, 0, s1>>>(BSUM, NB);
    scan3_kernel<<<NB, 256, 0, s1>>>(ROWPTR, BSUM, CUR, NNODES, E);
    fill_kernel<<<(E + T - 1) / T, T, 0, s1>>>(ei, DINV, CUR, ADJ, E);
    cudaEventRecord(eJoin, s1);

    // --- main: W1 prep + GEMM1 (two BN=128 N-halves) ---
    prep_w_kernel<<<(IN_C * HID_C + T - 1) / T, T>>>(W1, W1h, W1l, IN_C, HID_C);
    gemm_mma_kernel<128, false><<<dim3(1, MB), 256, SMEM_BN128>>>(
        x, W1h, W1l, H1, NNODES, IN_C, IN_C, HID_C, 0);
    cudaEventRecord(e1a, 0);

    gemm_mma_kernel<128, false><<<dim3(1, MB), 256, SMEM_BN128>>>(
        x, W1h, W1l, H1, NNODES, IN_C, IN_C, HID_C, 128);

    // --- s1: gather1a (features 0-127) then gemm2 K-half 0 ---
    cudaStreamWaitEvent(s1, e1a, 0);
    gather4_kernel<HID_C, 4, true><<<(NNODES + 3) / 4, dim3(32, 4), 0, s1>>>(
        (const float4*)H1, ROWPTR, ADJ, DINV, (const float4*)b1, (float4*)A1, 0);
    gemm_mma_kernel<128, false><<<dim3(1, MB), 256, SMEM_BN128, s1>>>(
        A1, W2h, W2l, H2, NNODES, HID_C, 128, OUT_C, 0);
    cudaEventRecord(eK0, s1);

    // --- main: gather1b (features 128-255), then gemm2 K-half 1 (accum) ---
    cudaStreamWaitEvent(0, eJoin, 0);
    gather4_kernel<HID_C, 4, true><<<(NNODES + 3) / 4, dim3(32, 4)>>>(
        (const float4*)H1, ROWPTR, ADJ, DINV, (const float4*)b1, (float4*)A1, 32);

    cudaStreamWaitEvent(0, eK0, 0);
    gemm_mma_kernel<128, true><<<dim3(1, MB), 256, SMEM_BN128>>>(
        A1 + 128, W2h + 128, W2l + 128, H2, NNODES, HID_C, 128, OUT_C, 0);
    cudaEventRecord(e2k1, 0);

    // --- gather2 halves in parallel on the two streams ---
    cudaStreamWaitEvent(s1, e2k1, 0);
    gather4_kernel<OUT_C, 8, false><<<(NNODES + 7) / 8, dim3(16, 8), 0, s1>>>(
        (const float4*)H2, ROWPTR, ADJ, DINV, (const float4*)b2, (float4*)out, 0);
    cudaEventRecord(eS2, s1);

    gather4_kernel<OUT_C, 8, false><<<(NNODES + 7) / 8, dim3(16, 8)>>>(
        (const float4*)H2, ROWPTR, ADJ, DINV, (const float4*)b2, (float4*)out, 16);

    // --- join s1 back into main before capture end ---
    cudaStreamWaitEvent(0, eS2, 0);
}

// round 17
// speedup vs baseline: 1.0436x; 1.0436x over previous
#include <cuda_runtime.h>
#include <cuda_bf16.h>
#include <cstdint>

#define NNODES 50000
#define MAXE   800000
#define IN_C   512
#define HID_C  256
#define OUT_C  128

// ---------------------------------------------------------------------------
// Scratch (device globals — allocation is forbidden)
// ---------------------------------------------------------------------------
__device__ float g_H1[(size_t)NNODES * HID_C];
__device__ float g_A1[(size_t)NNODES * HID_C];
__device__ float g_H2[(size_t)NNODES * OUT_C];
__device__ int   g_CNT[NNODES];
__device__ float g_DINV[NNODES];
__device__ int   g_ROWPTR[NNODES + 1];
__device__ int   g_CUR[NNODES];
__device__ int   g_BSUM[256];
__device__ int2  g_ADJ[MAXE];
__device__ int   g_is64;
// Pre-split, pre-transposed weights: Wt[n][k] (K-major = mma .col layout)
__device__ __nv_bfloat16 g_W1h[HID_C * IN_C];
__device__ __nv_bfloat16 g_W1l[HID_C * IN_C];
__device__ __nv_bfloat16 g_W2h[OUT_C * HID_C];
__device__ __nv_bfloat16 g_W2l[OUT_C * HID_C];

// ---------------------------------------------------------------------------
// PTX helpers
// ---------------------------------------------------------------------------
__device__ __forceinline__ uint32_t smem_u32(const void* p) {
    uint32_t a;
    asm("{ .reg .u64 t; cvta.to.shared.u64 t, %1; cvt.u32.u64 %0, t; }" : "=r"(a) : "l"(p));
    return a;
}

#define LDMX4(r, addr) \
    asm volatile("ldmatrix.sync.aligned.m8n8.x4.shared.b16 {%0,%1,%2,%3}, [%4];" \
        : "=r"((r)[0]), "=r"((r)[1]), "=r"((r)[2]), "=r"((r)[3]) : "r"(addr))

#define MMA16816(d, a, b0, b1) \
    asm volatile("mma.sync.aligned.m16n8k16.row.col.f32.bf16.bf16.f32 " \
        "{%0,%1,%2,%3}, {%4,%5,%6,%7}, {%8,%9}, {%0,%1,%2,%3};" \
        : "+f"((d)[0]), "+f"((d)[1]), "+f"((d)[2]), "+f"((d)[3]) \
        : "r"((a)[0]), "r"((a)[1]), "r"((a)[2]), "r"((a)[3]), "r"(b0), "r"(b1))

// ---------------------------------------------------------------------------
// Edge index decoding (int64 vs int32, detected once per launch)
// ---------------------------------------------------------------------------
__device__ __forceinline__ int edge_at(const void* ei, long long i, int is64) {
    if (is64) return (int)((const long long*)ei)[i];
    return ((const int*)ei)[i];
}

__global__ void detect_kernel(const void* ei, long long maxv) {
    const long long* p = (const long long*)ei;
    int ok64 = 1;
    #pragma unroll
    for (int i = 0; i < 8; i++) {
        long long v = p[i];
        if (v < 0 || v >= maxv) ok64 = 0;
    }
    g_is64 = ok64;
}

// ---------------------------------------------------------------------------
// CSR build
// ---------------------------------------------------------------------------
__global__ void zero_cnt_kernel(int* p, int n) {
    int i = blockIdx.x * blockDim.x + threadIdx.x;
    if (i < n) p[i] = 0;
}

__global__ void hist_kernel(const void* __restrict__ ei, int* __restrict__ cnt, int E) {
    int e = (blockIdx.x * blockDim.x + threadIdx.x) * 2;
    if (e + 1 < E) {
        int d0 = edge_at(ei, (long long)E + e,     g_is64);
        int d1 = edge_at(ei, (long long)E + e + 1, g_is64);
        atomicAdd(&cnt[d0], 1);
        atomicAdd(&cnt[d1], 1);
    } else if (e < E) {
        atomicAdd(&cnt[edge_at(ei, (long long)E + e, g_is64)], 1);
    }
}

// Local exclusive scan per block + block totals; also computes dinv (fused).
__global__ void scan1_kernel(const int* __restrict__ cnt, int* __restrict__ locex,
                             int* __restrict__ bsum, float* __restrict__ dinv, int n)
{
    __shared__ int sh[256];
    int t = threadIdx.x;
    int i = blockIdx.x * 256 + t;
    int v = (i < n) ? cnt[i] : 0;
    sh[t] = v;
    __syncthreads();
    #pragma unroll
    for (int off = 1; off < 256; off <<= 1) {
        int u = (t >= off) ? sh[t - off] : 0;
        __syncthreads();
        sh[t] += u;
        __syncthreads();
    }
    if (i < n) {
        locex[i] = sh[t] - v;
        dinv[i]  = rsqrtf((float)v + 1.0f);
    }
    if (t == 255) bsum[blockIdx.x] = sh[255];
}

// Each block locally scans the (<=256) block sums, then applies its offset.
__global__ void scan3_kernel(int* __restrict__ rowptr, const int* __restrict__ bsum,
                             int* __restrict__ cur, int n, int nb, int E)
{
    __shared__ int sh[256];
    int t = threadIdx.x;
    int v = (t < nb) ? bsum[t] : 0;
    sh[t] = v;
    __syncthreads();
    #pragma unroll
    for (int off = 1; off < 256; off <<= 1) {
        int u = (t >= off) ? sh[t - off] : 0;
        __syncthreads();
        sh[t] += u;
        __syncthreads();
    }
    int boff = (blockIdx.x == 0) ? 0 : sh[blockIdx.x - 1];
    int i = blockIdx.x * 256 + t;
    if (i < n) {
        int r = rowptr[i] + boff;
        rowptr[i] = r;
        cur[i] = r;
    }
    if (blockIdx.x == 0 && t == 0) rowptr[n] = E;
}

__global__ void fill_kernel(const void* __restrict__ ei, const float* __restrict__ dinv,
                            int* __restrict__ cur, int2* __restrict__ adj, int E)
{
    int e = blockIdx.x * blockDim.x + threadIdx.x;
    if (e >= E) return;
    int is64 = g_is64;
    int s = edge_at(ei, e, is64);
    int d = edge_at(ei, (long long)E + e, is64);
    int pos = atomicAdd(&cur[d], 1);
    float w = dinv[s] * dinv[d];
    adj[pos] = make_int2(s, __float_as_int(w));
}

// ---------------------------------------------------------------------------
// Weight prep: W[k][n] (fp32) -> Wt_hi/Wt_lo[n][k] (bf16, K-major)
// ---------------------------------------------------------------------------
__global__ void prep_w_kernel(const float* __restrict__ W,
                              __nv_bfloat16* __restrict__ Wh,
                              __nv_bfloat16* __restrict__ Wl, int K, int N)
{
    int idx = blockIdx.x * blockDim.x + threadIdx.x;
    if (idx >= K * N) return;
    int n = idx / K, k = idx - n * K;
    float w = W[(size_t)k * N + n];
    __nv_bfloat16 h = __float2bfloat16_rn(w);
    float lo = w - __bfloat162float(h);
    Wh[idx] = h;
    Wl[idx] = __float2bfloat16_rn(lo);
}

// ---------------------------------------------------------------------------
// mma.sync bf16 3-product GEMM, double-buffered smem + register prefetch.
// C[M,N] = A[M,K](fp32) @ Wt[N,K]^T. CTA tile 128x128, BK=32, 256 threads,
// 8 warps 2m x 4n (warp 64x32). nOff shifts the N-column window.
// ---------------------------------------------------------------------------
#define SSTR 40

template<int BN>
__global__ __launch_bounds__(256) void gemm_mma_kernel(
    const float* __restrict__ A,
    const __nv_bfloat16* __restrict__ Wh, const __nv_bfloat16* __restrict__ Wl,
    float* __restrict__ C, int M, int K, int Nn, int nOff)
{
    constexpr int TAe = 128 * SSTR;
    constexpr int TBe = BN * SSTR;
    constexpr int MT  = (BN == 128) ? 4 : 2;
    constexpr int RB  = BN / 64;

    extern __shared__ __nv_bfloat16 dsm[];
    __nv_bfloat16* sAh[2] = { dsm,            dsm + TAe };
    __nv_bfloat16* sAl[2] = { dsm + 2 * TAe,  dsm + 3 * TAe };
    __nv_bfloat16* sBh[2] = { dsm + 4 * TAe,  dsm + 4 * TAe + TBe };
    __nv_bfloat16* sBl[2] = { dsm + 4 * TAe + 2 * TBe, dsm + 4 * TAe + 3 * TBe };

    const int tid  = threadIdx.x;
    const int wid  = tid >> 5;
    const int lane = tid & 31;
    const int rowBase = blockIdx.y * 128;
    const int colBase = blockIdx.x * BN + nOff;
    const int warpM = (BN == 128) ? (wid & 1) * 64 : (wid & 3) * 32;
    const int warpN = (BN == 128) ? (wid >> 1) * 32 : (wid >> 2) * 32;

    const uint32_t base = smem_u32(dsm);
    const uint32_t uAh[2] = { base,                     base + TAe * 2 };
    const uint32_t uAl[2] = { base + 4 * TAe,           base + 6 * TAe };
    const uint32_t uBh[2] = { base + 8 * TAe,           base + 8 * TAe + TBe * 2 };
    const uint32_t uBl[2] = { base + 8 * TAe + 4 * TBe, base + 8 * TAe + 6 * TBe };

    const int lrA = lane & 15;
    const int lkA = (lane >> 4) << 3;
    const int lnB = (lane & 7) + ((lane >> 4) << 3);
    const int lkB = ((lane >> 3) & 1) << 3;

    const int aRow = tid >> 1, aCol = (tid & 1) * 16;
    const int bRow = tid >> 2, bCol = (tid & 3) * 8;
    const bool aOk = (rowBase + aRow) < M;

    float acc[MT][4][4];
    #pragma unroll
    for (int mt = 0; mt < MT; mt++)
        #pragma unroll
        for (int nt = 0; nt < 4; nt++)
            #pragma unroll
            for (int i = 0; i < 4; i++) acc[mt][nt][i] = 0.0f;

    float4 aR[4];
    uint4  bhR[RB], blR[RB];

    auto loadT = [&](int k0) {
        const float* arow = A + (size_t)(rowBase + aRow) * K + k0 + aCol;
        #pragma unroll
        for (int i = 0; i < 4; i++)
            aR[i] = aOk ? *(const float4*)(arow + i * 4) : make_float4(0.f, 0.f, 0.f, 0.f);
        #pragma unroll
        for (int r2 = 0; r2 < RB; r2++) {
            const size_t gb = (size_t)(colBase + bRow + r2 * 64) * K + k0 + bCol;
            bhR[r2] = *(const uint4*)(Wh + gb);
            blR[r2] = *(const uint4*)(Wl + gb);
        }
    };

    auto storeT = [&](int buf) {
        #pragma unroll
        for (int i = 0; i < 4; i++) {
            float4 v = aR[i];
            __nv_bfloat162 h0 = __floats2bfloat162_rn(v.x, v.y);
            __nv_bfloat162 h1 = __floats2bfloat162_rn(v.z, v.w);
            __nv_bfloat162 l0 = __floats2bfloat162_rn(v.x - __bfloat162float(h0.x),
                                                      v.y - __bfloat162float(h0.y));
            __nv_bfloat162 l1 = __floats2bfloat162_rn(v.z - __bfloat162float(h1.x),
                                                      v.w - __bfloat162float(h1.y));
            int off = aRow * SSTR + aCol + i * 4;
            *(__nv_bfloat162*)&sAh[buf][off]     = h0;
            *(__nv_bfloat162*)&sAh[buf][off + 2] = h1;
            *(__nv_bfloat162*)&sAl[buf][off]     = l0;
            *(__nv_bfloat162*)&sAl[buf][off + 2] = l1;
        }
        #pragma unroll
        for (int r2 = 0; r2 < RB; r2++) {
            int off = (bRow + r2 * 64) * SSTR + bCol;
            *(uint4*)&sBh[buf][off] = bhR[r2];
            *(uint4*)&sBl[buf][off] = blR[r2];
        }
    };

    auto compute = [&](int buf) {
        #pragma unroll
        for (int ks = 0; ks < 2; ks++) {
            uint32_t ah[MT][4], al[MT][4], bh[2][4], bl[2][4];
            #pragma unroll
            for (int mt = 0; mt < MT; mt++) {
                uint32_t off = (uint32_t)((warpM + mt * 16 + lrA) * SSTR + ks * 16 + lkA) * 2;
                LDMX4(ah[mt], uAh[buf] + off);
                LDMX4(al[mt], uAl[buf] + off);
            }
            #pragma unroll
            for (int np = 0; np < 2; np++) {
                uint32_t off = (uint32_t)((warpN + np * 16 + lnB) * SSTR + ks * 16 + lkB) * 2;
                LDMX4(bh[np], uBh[buf] + off);
                LDMX4(bl[np], uBl[buf] + off);
            }
            #pragma unroll
            for (int mt = 0; mt < MT; mt++)
                #pragma unroll
                for (int np = 0; np < 2; np++)
                    #pragma unroll
                    for (int h = 0; h < 2; h++) {
                        int nt = np * 2 + h;
                        MMA16816(acc[mt][nt], ah[mt], bh[np][h*2], bh[np][h*2+1]);
                        MMA16816(acc[mt][nt], ah[mt], bl[np][h*2], bl[np][h*2+1]);
                        MMA16816(acc[mt][nt], al[mt], bh[np][h*2], bh[np][h*2+1]);
                    }
        }
    };

    const int KI = K >> 5;

    loadT(0);
    storeT(0);
    __syncthreads();
    if (KI > 1) loadT(32);

    for (int it = 0; it < KI; it++) {
        compute(it & 1);
        if (it + 1 < KI) {
            storeT((it + 1) & 1);
            __syncthreads();
            if (it + 2 < KI) loadT((it + 2) << 5);
        }
    }

    #pragma unroll
    for (int mt = 0; mt < MT; mt++) {
        int r0 = rowBase + warpM + mt * 16 + (lane >> 2);
        int r1 = r0 + 8;
        #pragma unroll
        for (int nt = 0; nt < 4; nt++) {
            int c = colBase + warpN + nt * 8 + (lane & 3) * 2;
            if (r0 < M) *(float2*)&C[(size_t)r0 * Nn + c] = make_float2(acc[mt][nt][0], acc[mt][nt][1]);
            if (r1 < M) *(float2*)&C[(size_t)r1 * Nn + c] = make_float2(acc[mt][nt][2], acc[mt][nt][3]);
        }
    }
}

#define SMEM_BN128 ((4 * 128 * SSTR + 4 * 128 * SSTR) * 2)   // 81920

// ---------------------------------------------------------------------------
// CSR gather over a feature window [f4base, f4base+blockDim.x) (float4 units).
// ---------------------------------------------------------------------------
template<int C, int NPB, bool RELU>
__global__ __launch_bounds__(256) void gather4_kernel(
    const float4* __restrict__ H4, const int* __restrict__ rowptr,
    const int2* __restrict__ adj, const float* __restrict__ dinv,
    const float4* __restrict__ bias4, float4* __restrict__ out4, int f4base)
{
    const int F4 = C / 4;
    int v  = blockIdx.x * NPB + threadIdx.y;
    int fx = f4base + threadIdx.x;
    if (v >= NNODES) return;

    float dv = dinv[v];
    float ws = dv * dv;
    float4 acc = H4[(size_t)v * F4 + fx];
    acc.x *= ws; acc.y *= ws; acc.z *= ws; acc.w *= ws;

    int j   = rowptr[v];
    int end = rowptr[v + 1];

    for (; j + 3 < end; j += 4) {
        int2 a0 = __ldg(&adj[j]);
        int2 a1 = __ldg(&adj[j + 1]);
        int2 a2 = __ldg(&adj[j + 2]);
        int2 a3 = __ldg(&adj[j + 3]);
        float4 h0 = H4[(size_t)a0.x * F4 + fx];
        float4 h1 = H4[(size_t)a1.x * F4 + fx];
        float4 h2 = H4[(size_t)a2.x * F4 + fx];
        float4 h3 = H4[(size_t)a3.x * F4 + fx];
        float w0 = __int_as_float(a0.y), w1 = __int_as_float(a1.y);
        float w2 = __int_as_float(a2.y), w3 = __int_as_float(a3.y);
        acc.x = fmaf(h0.x, w0, fmaf(h1.x, w1, fmaf(h2.x, w2, fmaf(h3.x, w3, acc.x))));
        acc.y = fmaf(h0.y, w0, fmaf(h1.y, w1, fmaf(h2.y, w2, fmaf(h3.y, w3, acc.y))));
        acc.z = fmaf(h0.z, w0, fmaf(h1.z, w1, fmaf(h2.z, w2, fmaf(h3.z, w3, acc.z))));
        acc.w = fmaf(h0.w, w0, fmaf(h1.w, w1, fmaf(h2.w, w2, fmaf(h3.w, w3, acc.w))));
    }
    for (; j < end; j++) {
        int2 a0 = __ldg(&adj[j]);
        float4 h0 = H4[(size_t)a0.x * F4 + fx];
        float w0 = __int_as_float(a0.y);
        acc.x = fmaf(h0.x, w0, acc.x);
        acc.y = fmaf(h0.y, w0, acc.y);
        acc.z = fmaf(h0.z, w0, acc.z);
        acc.w = fmaf(h0.w, w0, acc.w);
    }

    float4 b = bias4[fx];
    acc.x += b.x; acc.y += b.y; acc.z += b.z; acc.w += b.w;
    if (RELU) {
        acc.x = fmaxf(acc.x, 0.f); acc.y = fmaxf(acc.y, 0.f);
        acc.z = fmaxf(acc.z, 0.f); acc.w = fmaxf(acc.w, 0.f);
    }
    out4[(size_t)v * F4 + fx] = acc;
}

// ---------------------------------------------------------------------------
// Launch schedule:
//   s1  : prep_w2, CSR chain, [e1a] gather1a(f0-127), rec eS1,
//         [e2] gather2a(f0-63), rec eS2
//   main: prep_w1, gemm1a, rec e1a, gemm1b, [eJoin] gather1b(f128-255),
//         [eS1] gemm2 (single BN=128), rec e2, gather2b(f64-127), [eS2]
// ---------------------------------------------------------------------------
extern "C" void kernel_launch(void* const* d_in, const int* in_sizes, int n_in,
                              void* d_out, int out_size)
{
    const float* x  = (const float*)d_in[0];
    const void*  ei = d_in[1];
    const float* W1 = (const float*)d_in[2];
    const float* b1 = (const float*)d_in[3];
    const float* W2 = (const float*)d_in[4];
    const float* b2 = (const float*)d_in[5];
    float* out = (float*)d_out;

    const int E = in_sizes[1] / 2;

    float *H1, *A1, *H2, *DINV;
    int *CNT, *ROWPTR, *CUR, *BSUM;
    int2 *ADJ;
    __nv_bfloat16 *W1h, *W1l, *W2h, *W2l;
    cudaGetSymbolAddress((void**)&H1,     g_H1);
    cudaGetSymbolAddress((void**)&A1,     g_A1);
    cudaGetSymbolAddress((void**)&H2,     g_H2);
    cudaGetSymbolAddress((void**)&CNT,    g_CNT);
    cudaGetSymbolAddress((void**)&DINV,   g_DINV);
    cudaGetSymbolAddress((void**)&ROWPTR, g_ROWPTR);
    cudaGetSymbolAddress((void**)&CUR,    g_CUR);
    cudaGetSymbolAddress((void**)&BSUM,   g_BSUM);
    cudaGetSymbolAddress((void**)&ADJ,    g_ADJ);
    cudaGetSymbolAddress((void**)&W1h,    g_W1h);
    cudaGetSymbolAddress((void**)&W1l,    g_W1l);
    cudaGetSymbolAddress((void**)&W2h,    g_W2h);
    cudaGetSymbolAddress((void**)&W2l,    g_W2l);

    cudaFuncSetAttribute(gemm_mma_kernel<128>,
                         cudaFuncAttributeMaxDynamicSharedMemorySize, SMEM_BN128);

    static cudaStream_t s1 = nullptr;
    static cudaEvent_t  eFork = nullptr, eJoin = nullptr, e1a = nullptr,
                        eS1 = nullptr, e2 = nullptr, eS2 = nullptr;
    if (s1 == nullptr) {
        cudaStreamCreateWithFlags(&s1, cudaStreamNonBlocking);
        cudaEventCreateWithFlags(&eFork, cudaEventDisableTiming);
        cudaEventCreateWithFlags(&eJoin, cudaEventDisableTiming);
        cudaEventCreateWithFlags(&e1a,   cudaEventDisableTiming);
        cudaEventCreateWithFlags(&eS1,   cudaEventDisableTiming);
        cudaEventCreateWithFlags(&e2,    cudaEventDisableTiming);
        cudaEventCreateWithFlags(&eS2,   cudaEventDisableTiming);
    }

    const int T = 256;
    const int NB = (NNODES + 255) / 256;   // 196
    const int MB = (NNODES + 127) / 128;   // 391

    // --- fork: W2 prep + CSR build on s1 ---
    cudaEventRecord(eFork, 0);
    cudaStreamWaitEvent(s1, eFork, 0);

    prep_w_kernel<<<(HID_C * OUT_C + T - 1) / T, T, 0, s1>>>(W2, W2h, W2l, HID_C, OUT_C);
    detect_kernel<<<1, 1, 0, s1>>>(ei, (long long)NNODES);
    zero_cnt_kernel<<<NB, T, 0, s1>>>(CNT, NNODES);
    hist_kernel<<<(E / 2 + T) / T, T, 0, s1>>>(ei, CNT, E);
    scan1_kernel<<<NB, 256, 0, s1>>>(CNT, ROWPTR, BSUM, DINV, NNODES);
    scan3_kernel<<<NB, 256, 0, s1>>>(ROWPTR, BSUM, CUR, NNODES, NB, E);
    fill_kernel<<<(E + T - 1) / T, T, 0, s1>>>(ei, DINV, CUR, ADJ, E);
    cudaEventRecord(eJoin, s1);

    // --- main: W1 prep + GEMM1 (two BN=128 N-halves) ---
    prep_w_kernel<<<(IN_C * HID_C + T - 1) / T, T>>>(W1, W1h, W1l, IN_C, HID_C);
    gemm_mma_kernel<128><<<dim3(1, MB), 256, SMEM_BN128>>>(
        x, W1h, W1l, H1, NNODES, IN_C, HID_C, 0);
    cudaEventRecord(e1a, 0);

    gemm_mma_kernel<128><<<dim3(1, MB), 256, SMEM_BN128>>>(
        x, W1h, W1l, H1, NNODES, IN_C, HID_C, 128);

    // --- s1: gather1a (features 0-127), hidden under gemm1b ---
    cudaStreamWaitEvent(s1, e1a, 0);
    gather4_kernel<HID_C, 4, true><<<(NNODES + 3) / 4, dim3(32, 4), 0, s1>>>(
        (const float4*)H1, ROWPTR, ADJ, DINV, (const float4*)b1, (float4*)A1, 0);
    cudaEventRecord(eS1, s1);

    // --- main: gather1b (features 128-255) ---
    cudaStreamWaitEvent(0, eJoin, 0);
    gather4_kernel<HID_C, 4, true><<<(NNODES + 3) / 4, dim3(32, 4)>>>(
        (const float4*)H1, ROWPTR, ADJ, DINV, (const float4*)b1, (float4*)A1, 32);

    // --- main: single gemm2 (BN=128 covers all OUT_C cols; reads A1 once) ---
    cudaStreamWaitEvent(0, eS1, 0);
    gemm_mma_kernel<128><<<dim3(1, MB), 256, SMEM_BN128>>>(
        A1, W2h, W2l, H2, NNODES, HID_C, OUT_C, 0);
    cudaEventRecord(e2, 0);

    // --- gather2 halves in parallel on the two streams ---
    cudaStreamWaitEvent(s1, e2, 0);
    gather4_kernel<OUT_C, 8, false><<<(NNODES + 7) / 8, dim3(16, 8), 0, s1>>>(
        (const float4*)H2, ROWPTR, ADJ, DINV, (const float4*)b2, (float4*)out, 0);
    cudaEventRecord(eS2, s1);

    gather4_kernel<OUT_C, 8, false><<<(NNODES + 7) / 8, dim3(16, 8)>>>(
        (const float4*)H2, ROWPTR, ADJ, DINV, (const float4*)b2, (float4*)out, 16);

    // --- join s1 back into main before capture end ---
    cudaStreamWaitEvent(0, eS2, 0);
}